// round 8
// baseline (speedup 1.0000x reference)
#include <cuda_runtime.h>
#include <cuda_bf16.h>
#include <math.h>
#include <stdint.h>

// ---------------------------------------------------------------------------
// Problem constants (match reference)
// ---------------------------------------------------------------------------
#define S_LEN   4096
#define BATCH   4
#define HCH     256
#define ICH     512
#define NDEPTH  8
#define KWIDTH  7
#define NOUT    256
#define LOGC    6.4798891f   // log(S/2/pi)

// ---------------------------------------------------------------------------
// Scratch (device globals; no cudaMalloc allowed)
// ---------------------------------------------------------------------------
__device__ float g_A  [BATCH*HCH*S_LEN];
__device__ float g_Bc [BATCH*HCH*S_LEN];
__device__ float g_O  [BATCH*HCH*S_LEN];
__device__ float g_T1 [BATCH*ICH*S_LEN];
__device__ float g_T2 [BATCH*ICH*S_LEN];
__device__ float g_D  [BATCH*HCH*S_LEN];
__device__ float g_P  [BATCH*HCH*S_LEN];
__device__ float g_S  [BATCH*HCH*S_LEN];
__device__ float g_NLL[BATCH*S_LEN];

// ---------------------------------------------------------------------------
// Tiny init launch (aligns ncu -s 5 -c 1 onto the conv kernels)
// ---------------------------------------------------------------------------
__global__ void init_kernel(float* __restrict__ nll)
{
    int i = blockIdx.x * blockDim.x + threadIdx.x;
    if (i < BATCH * S_LEN) nll[i] = 0.f;
}

// ---------------------------------------------------------------------------
// Embedding gather
// ---------------------------------------------------------------------------
__global__ void embed_kernel(const float* __restrict__ emb,
                             const int*   __restrict__ inp,
                             float* __restrict__ A, float* __restrict__ Bc)
{
    int tid = blockIdx.x * blockDim.x + threadIdx.x;     // B*S threads
    int b = tid >> 12;
    int s = tid & (S_LEN - 1);
    int tok = inp[tid];
    const float* e = emb + (size_t)tok * (2 * HCH);
    size_t base = ((size_t)b * HCH) * S_LEN + s;
#pragma unroll 4
    for (int h = 0; h < HCH; h++) {
        A [base + (size_t)h * S_LEN] = e[h];
        Bc[base + (size_t)h * S_LEN] = e[HCH + h];
    }
}

// ---------------------------------------------------------------------------
// out = b + pos_embd
// ---------------------------------------------------------------------------
__global__ void addpos_kernel(const float* __restrict__ Bc, float* __restrict__ O)
{
    int idx = blockIdx.x * blockDim.x + threadIdx.x;     // B*H*S
    int s = idx & (S_LEN - 1);
    int h = (idx >> 12) & (HCH - 1);
    float feat = (float)(h + 1);
    float additive = (float)((h + 1) & 1);
    float fe0 = (feat - additive) * 0.5f * (8.0f / (float)HCH) - LOGC;
    float fe  = expf(fe0) + additive * 3.14159265358979f;
    float pe  = sinf((float)(s + 1) * fe) * 0.125f;
    O[idx] = Bc[idx] + pe;
}

// ---------------------------------------------------------------------------
// cp.async helper (16B, src-size 0 => zero-fill)
// ---------------------------------------------------------------------------
__device__ __forceinline__ void cp16(uint32_t saddr, const void* gaddr, bool pred)
{
    int sz = pred ? 16 : 0;
    asm volatile("cp.async.cg.shared.global [%0], [%1], 16, %2;\n"
                 :: "r"(saddr), "l"(gaddr), "r"(sz));
}
__device__ __forceinline__ void cp_commit()
{
    asm volatile("cp.async.commit_group;\n" ::: "memory");
}
template<int N>
__device__ __forceinline__ void cp_wait()
{
    asm volatile("cp.async.wait_group %0;\n" :: "n"(N) : "memory");
}

// ---------------------------------------------------------------------------
// Tensor-core causal-conv / GEMM (tf32 mma.sync.m16n8k8).
//   Y[b,o,s] = sum_ci sum_k W[o,ci,k] * X[b,ci,s-(KW-1)+k]   (zero left pad)
// CTA tile: 256 out x 128 seq. 8 warps = 4(M) x 2(N), warp tile 64 x 64.
// K pipeline: TK=8 cin per stage (mma-k == stage-k, no inner ks loop),
// NSTG-stage cp.async ring buffer. LDS/mma = 1.0 (vs 1.5 at 64x32 warp tile).
// ---------------------------------------------------------------------------
template<int KW, int NSTG>
__global__ void __launch_bounds__(256, 1)
mma_conv(const float* __restrict__ X, const float* __restrict__ W,
         float* __restrict__ Y, int Cin, int Cout)
{
    constexpr int TM = 256, TN = 128, TK = 8;
    constexpr int SHIFT = (KW > 1) ? 8 : 0;        // aligned halo lead-in
    constexpr int XW   = TN + SHIFT;               // loaded width per ci row
    constexpr int XSTR = TN + 8;                   // 136: bank-safe stride
    constexpr int WROW = TK * KW;                  // contiguous gmem floats per o
    constexpr int WSTR = WROW + 4;                 // 60 / 12: bank-safe, 16B-mult
    constexpr int XV   = XW / 4;                   // vec4 per ci row
    constexpr int WV   = WROW / 4;                 // vec4 per o row

    extern __shared__ float smem[];
    float* Xs = smem;                              // [NSTG][TK][XSTR]
    float* Ws = smem + NSTG * TK * XSTR;           // [NSTG][TM][WSTR]

    const int s0 = blockIdx.x * TN;
    const int o0 = blockIdx.y * TM;
    const int bb = blockIdx.z;
    const float* Xb = X + (size_t)bb * Cin * S_LEN;
    float*       Yb = Y + (size_t)bb * Cout * S_LEN;

    const int tid   = threadIdx.x;
    const int lane  = tid & 31;
    const int wid   = tid >> 5;
    const int warpM = wid >> 1;                    // 0..3
    const int warpN = wid & 1;                     // 0..1
    const int gid   = lane >> 2;                   // 0..7
    const int tig   = lane & 3;                    // 0..3

    const uint32_t xs_base = (uint32_t)__cvta_generic_to_shared(Xs);
    const uint32_t ws_base = (uint32_t)__cvta_generic_to_shared(Ws);

    const int NT = Cin / TK;                       // >= 32 always

    // stage loader (all 256 threads convergent; commit is uniform)
    auto load_stage = [&](int it, int buf) {
        int ci0 = it * TK;
        // X tile: TK rows x XW floats, starting at s0-SHIFT (zfill OOB)
        for (int i = tid; i < TK * XV; i += 256) {
            int ci = i / XV;
            int v  = i - ci * XV;
            int sg = s0 - SHIFT + v * 4;
            const float* gp = Xb + (size_t)(ci0 + ci) * S_LEN + sg;
            uint32_t sa = xs_base + (uint32_t)(((buf * TK + ci) * XSTR + v * 4) * 4);
            cp16(sa, gp, sg >= 0);
        }
        // W tile: TM rows x WROW floats (contiguous per o)
        for (int i = tid; i < TM * WV; i += 256) {
            int o = i / WV;
            int v = i - o * WV;
            const float* gp = W + (size_t)(o0 + o) * Cin * KW + (size_t)ci0 * KW + v * 4;
            uint32_t sa = ws_base + (uint32_t)(((buf * TM + o) * WSTR + v * 4) * 4);
            cp16(sa, gp, true);
        }
        cp_commit();
    };

    float acc[4][8][4];
#pragma unroll
    for (int mi = 0; mi < 4; mi++)
#pragma unroll
        for (int ni = 0; ni < 8; ni++)
#pragma unroll
            for (int r = 0; r < 4; r++) acc[mi][ni][r] = 0.f;

    // prologue: fill NSTG-1 stages
#pragma unroll
    for (int p = 0; p < NSTG - 1; p++) load_stage(p, p);

    int buf = 0;                                   // stage being consumed
    int nbuf = NSTG - 1;                           // stage to fill next
    for (int it = 0; it < NT; it++) {
        if (it + NSTG - 1 < NT) {
            load_stage(it + NSTG - 1, nbuf);
            if (++nbuf == NSTG) nbuf = 0;
        }
        // ensure stage `it` is complete: allow pending prefetches only
        if (NSTG >= 3 && it + 2 < NT) cp_wait<2>();
        else if (it + 1 < NT)         cp_wait<1>();
        else                          cp_wait<0>();
        __syncthreads();

        const uint32_t* Wt = (const uint32_t*)(Ws + buf * TM * WSTR);
        const uint32_t* Xt = (const uint32_t*)(Xs + buf * TK * XSTR);

#pragma unroll
        for (int k = 0; k < KW; k++) {
            // A fragments (W): rows = out, cols = ci within the 8-block
            uint32_t Af[4][4];
#pragma unroll
            for (int mi = 0; mi < 4; mi++) {
                const uint32_t* w0p = Wt + (warpM * 64 + mi * 16 + gid) * WSTR + tig * KW + k;
                Af[mi][0] = w0p[0];
                Af[mi][1] = w0p[8 * WSTR];
                Af[mi][2] = w0p[4 * KW];
                Af[mi][3] = w0p[8 * WSTR + 4 * KW];
            }
            // B fragments (X): rows = ci (K), cols = seq (N)
            uint32_t Bf[8][2];
            const int tofs = SHIFT - KW + 1 + k;
#pragma unroll
            for (int ni = 0; ni < 8; ni++) {
                const uint32_t* xp = Xt + tig * XSTR + warpN * 64 + ni * 8 + gid + tofs;
                Bf[ni][0] = xp[0];
                Bf[ni][1] = xp[4 * XSTR];
            }
#pragma unroll
            for (int mi = 0; mi < 4; mi++)
#pragma unroll
                for (int ni = 0; ni < 8; ni++) {
                    float* d = acc[mi][ni];
                    asm volatile(
                        "mma.sync.aligned.m16n8k8.row.col.f32.tf32.tf32.f32 "
                        "{%0,%1,%2,%3}, {%4,%5,%6,%7}, {%8,%9}, {%0,%1,%2,%3};\n"
                        : "+f"(d[0]), "+f"(d[1]), "+f"(d[2]), "+f"(d[3])
                        : "r"(Af[mi][0]), "r"(Af[mi][1]), "r"(Af[mi][2]), "r"(Af[mi][3]),
                          "r"(Bf[ni][0]), "r"(Bf[ni][1]));
                }
        }
        __syncthreads();
        if (++buf == NSTG) buf = 0;
    }

    // epilogue: write fp32
#pragma unroll
    for (int mi = 0; mi < 4; mi++) {
        int o = o0 + warpM * 64 + mi * 16 + gid;
#pragma unroll
        for (int ni = 0; ni < 8; ni++) {
            int s = s0 + warpN * 64 + ni * 8 + 2 * tig;
            float2 v0 = make_float2(acc[mi][ni][0], acc[mi][ni][1]);
            float2 v1 = make_float2(acc[mi][ni][2], acc[mi][ni][3]);
            *(float2*)&Yb[(size_t)o * S_LEN + s]       = v0;
            *(float2*)&Yb[(size_t)(o + 8) * S_LEN + s] = v1;
        }
    }
}

// ---------------------------------------------------------------------------
// Block reduction helper (256 threads = 8 warps)
// ---------------------------------------------------------------------------
__device__ __forceinline__ float block_reduce(float v, float* sm)
{
    int lane = threadIdx.x & 31;
    int w    = threadIdx.x >> 5;
#pragma unroll
    for (int o = 16; o > 0; o >>= 1) v += __shfl_xor_sync(0xffffffffu, v, o);
    if (lane == 0) sm[w] = v;
    __syncthreads();
    if (w == 0) {
        float r = (lane < 8) ? sm[lane] : 0.f;
#pragma unroll
        for (int o = 4; o > 0; o >>= 1) r += __shfl_xor_sync(0xffffffffu, r, o);
        if (lane == 0) sm[32] = r;
    }
    __syncthreads();
    float out = sm[32];
    __syncthreads();
    return out;
}

// ---------------------------------------------------------------------------
// act_norm over the sequence axis; optional fused residual add.
// ---------------------------------------------------------------------------
__global__ void actnorm_kernel(const float* __restrict__ X,
                               const float* __restrict__ Res,
                               float* __restrict__ Y)
{
    __shared__ float sm[33];
    size_t row = blockIdx.x;
    const float4* x = (const float4*)(X + row * S_LEN);
    float4*       y = (float4*)(Y + row * S_LEN);
    int tid = threadIdx.x;

    float4 v[4];
    float sum = 0.f;
#pragma unroll
    for (int i = 0; i < 4; i++) {
        float4 t = x[tid + i * 256];
        t.x = fmaxf(t.x, 0.f); t.y = fmaxf(t.y, 0.f);
        t.z = fmaxf(t.z, 0.f); t.w = fmaxf(t.w, 0.f);
        v[i] = t;
        sum += (t.x + t.y) + (t.z + t.w);
    }
    sum = block_reduce(sum, sm);
    float mean = sum * (1.f / (float)S_LEN);

    float ssq = 0.f;
#pragma unroll
    for (int i = 0; i < 4; i++) {
        v[i].x -= mean; v[i].y -= mean; v[i].z -= mean; v[i].w -= mean;
        ssq += v[i].x * v[i].x + v[i].y * v[i].y + v[i].z * v[i].z + v[i].w * v[i].w;
    }
    ssq = block_reduce(ssq, sm);
    float scale = 64.f / (sqrtf(ssq) + 1e-5f);

    if (Res) {
        const float4* r = (const float4*)(Res + row * S_LEN);
#pragma unroll
        for (int i = 0; i < 4; i++) {
            float4 rv = r[tid + i * 256];
            float4 o;
            o.x = rv.x + v[i].x * scale;
            o.y = rv.y + v[i].y * scale;
            o.z = rv.z + v[i].z * scale;
            o.w = rv.w + v[i].w * scale;
            y[tid + i * 256] = o;
        }
    } else {
#pragma unroll
        for (int i = 0; i < 4; i++) {
            float4 o;
            o.x = v[i].x * scale; o.y = v[i].y * scale;
            o.z = v[i].z * scale; o.w = v[i].w * scale;
            y[tid + i * 256] = o;
        }
    }
}

// ---------------------------------------------------------------------------
// Gate: Tmp = Bc * (cumsum_h(D)/(s+1) + P) + Sb
// ---------------------------------------------------------------------------
__global__ void gate_kernel(const float* __restrict__ D, const float* __restrict__ P,
                            const float* __restrict__ Sb, const float* __restrict__ Bc,
                            float* __restrict__ Tmp)
{
    int tid = blockIdx.x * blockDim.x + threadIdx.x;     // B*S
    int b = tid >> 12;
    int s = tid & (S_LEN - 1);
    float inv = 1.f / (float)(s + 1);
    float acc = 0.f;
    size_t base = ((size_t)b * HCH) * S_LEN + s;
#pragma unroll 8
    for (int h = 0; h < HCH; h++) {
        size_t i = base + (size_t)h * S_LEN;
        acc += D[i];
        Tmp[i] = Bc[i] * (acc * inv + P[i]) + Sb[i];
    }
}

// ---------------------------------------------------------------------------
// Concat [a; b] over channels
// ---------------------------------------------------------------------------
__global__ void concat_kernel(const float* __restrict__ A, const float* __restrict__ Bc,
                              float* __restrict__ XC)
{
    int idx = blockIdx.x * blockDim.x + threadIdx.x;     // B*512*S
    int s = idx & (S_LEN - 1);
    int c = (idx >> 12) & 511;
    int b = idx >> 21;
    float v = (c < HCH) ? A [((size_t)b * HCH + c) * S_LEN + s]
                        : Bc[((size_t)b * HCH + (c - HCH)) * S_LEN + s];
    XC[idx] = v;
}

// ---------------------------------------------------------------------------
// Per-token NLL (online logsumexp) + deterministic mean
// ---------------------------------------------------------------------------
__global__ void loss_kernel(const float* __restrict__ logits,
                            const float* __restrict__ outb,
                            const int*   __restrict__ tgt,
                            float* __restrict__ nll)
{
    int tid = blockIdx.x * blockDim.x + threadIdx.x;     // B*S
    int b = tid >> 12;
    int s = tid & (S_LEN - 1);
    const float* lg = logits + ((size_t)b * NOUT) * S_LEN + s;
    int tg = tgt[tid];

    float m = -1e30f, se = 0.f, vt = 0.f;
    for (int o = 0; o < NOUT; o++) {
        float v = lg[(size_t)o * S_LEN] + outb[o];
        if (o == tg) vt = v;
        if (v > m) { se = se * expf(m - v) + 1.f; m = v; }
        else       { se += expf(v - m); }
    }
    nll[tid] = -(vt - m - logf(se));
}

__global__ void reduce_mean_kernel(const float* __restrict__ nll, float* __restrict__ out)
{
    __shared__ float sm[33];
    float v = 0.f;
    for (int i = threadIdx.x; i < BATCH * S_LEN; i += 256) v += nll[i];
    v = block_reduce(v, sm);
    if (threadIdx.x == 0) out[0] = v * (1.f / (float)(BATCH * S_LEN));
}

// ---------------------------------------------------------------------------
// Host orchestration
// ---------------------------------------------------------------------------
static const int SMEM7 = (3 * 8 * 136 + 3 * 256 * (8 * 7 + 4)) * 4;  // 197376 B
static const int SMEM1 = (3 * 8 * 136 + 3 * 256 * (8 * 1 + 4)) * 4;  //  49920 B

extern "C" void kernel_launch(void* const* d_in, const int* in_sizes, int n_in,
                              void* d_out, int out_size)
{
    const float* emb   = (const float*)d_in[0];
    const float* w0    = (const float*)d_in[1];
    const float* w1    = (const float*)d_in[2];
    const float* w2    = (const float*)d_in[3];
    const float* out_w = (const float*)d_in[4];
    const float* out_b = (const float*)d_in[5];
    const int*   inp   = (const int*)d_in[6];
    const int*   tgt   = (const int*)d_in[7];
    float* out = (float*)d_out;

    float *A, *Bc, *O, *T1, *T2, *D, *P, *Sb, *NLL;
    cudaGetSymbolAddress((void**)&A,  g_A);
    cudaGetSymbolAddress((void**)&Bc, g_Bc);
    cudaGetSymbolAddress((void**)&O,  g_O);
    cudaGetSymbolAddress((void**)&T1, g_T1);
    cudaGetSymbolAddress((void**)&T2, g_T2);
    cudaGetSymbolAddress((void**)&D,  g_D);
    cudaGetSymbolAddress((void**)&P,  g_P);
    cudaGetSymbolAddress((void**)&Sb, g_S);
    cudaGetSymbolAddress((void**)&NLL,g_NLL);

    cudaFuncSetAttribute((const void*)mma_conv<7,3>, cudaFuncAttributeMaxDynamicSharedMemorySize, SMEM7);
    cudaFuncSetAttribute((const void*)mma_conv<1,3>, cudaFuncAttributeMaxDynamicSharedMemorySize, SMEM1);

    // launch #1: init (aligns ncu -s 5 onto the conv kernels)
    init_kernel<<<(BATCH * S_LEN + 255) / 256, 256>>>(NLL);
    embed_kernel<<<(BATCH * S_LEN) / 256, 256>>>(emb, inp, A, Bc);

    float* pa = A;
    float* pb = Bc;
    for (int l = 0; l < NDEPTH; l++) {
        addpos_kernel<<<(BATCH * HCH * S_LEN) / 256, 256>>>(pb, O);
        for (int j = 0; j < 3; j++) {
            int wi = l * 3 + j;
            const float* cw0 = w0 + (size_t)wi * ICH * HCH;
            const float* cw1 = w1 + (size_t)wi * ICH * ICH * KWIDTH;
            const float* cw2 = w2 + (size_t)wi * HCH * ICH;
            float* dst = (j == 0) ? D : ((j == 1) ? P : Sb);

            mma_conv<1,3><<<dim3(S_LEN / 128, ICH / 256, BATCH), 256, SMEM1>>>(O,  cw0, T1, HCH, ICH);
            actnorm_kernel<<<BATCH * ICH, 256>>>(T1, nullptr, T1);
            mma_conv<7,3><<<dim3(S_LEN / 128, ICH / 256, BATCH), 256, SMEM7>>>(T1, cw1, T2, ICH, ICH);
            actnorm_kernel<<<BATCH * ICH, 256>>>(T2, nullptr, T2);
            mma_conv<1,3><<<dim3(S_LEN / 128, HCH / 256, BATCH), 256, SMEM1>>>(T2, cw2, dst, ICH, HCH);
        }
        gate_kernel<<<(BATCH * S_LEN) / 256, 256>>>(D, P, Sb, pb, O);
        actnorm_kernel<<<BATCH * HCH, 256>>>(O, pa, pa);
        float* t = pa; pa = pb; pb = t;
    }

    concat_kernel<<<(BATCH * 2 * HCH * S_LEN) / 256, 256>>>(pa, pb, T1);
    mma_conv<1,3><<<dim3(S_LEN / 128, NOUT / 256, BATCH), 256, SMEM1>>>(T1, out_w, D, 2 * HCH, NOUT);
    loss_kernel<<<(BATCH * S_LEN) / 256, 256>>>(D, out_b, tgt, NLL);
    reduce_mean_kernel<<<1, 256>>>(NLL, out);
}